// round 16
// baseline (speedup 1.0000x reference)
#include <cuda_runtime.h>
#include <cuda_fp16.h>

// ---------------------------------------------------------------------------
// GQNN: 2-layer SAGEConv (mean aggr) + fc head.
//   Padded direct binning (no scan, no CSR staging): one pass converts the
//   int64 edge list and bins src into slot[dst*CAP + k]. Degrees ~Poisson(32),
//   CAP=128 => P(overflow) < 1e-13; guard prevents OOB regardless.
//   Per layer: mean = gather of fp16 neighbor rows (fp32 accumulate),
//   h = relu(mean @ Wl + b + h_prev @ Wr) with packed f32x2 FMA.
// N = 100000, E = 3200000, HID = 64. 7 kernel launches total.
// NOTE: __device__ buffers are selected INSIDE device code (flag arg).
// ---------------------------------------------------------------------------

#define NMAX 100000
#define EMAX 3200000
#define CAP 128

__device__ __align__(16) float  g_agg[NMAX * 64];   // neighbor MEAN (fp32)
__device__ float  g_aggT[NMAX];                     // tau mean (layer 1 only)
__device__ __align__(16) float  g_h1[NMAX * 64];    // layer-1 output (fp32, self term)
__device__ __align__(16) __half g_xh[NMAX * 64];    // fp16 copy of x (gather src L1)
__device__ __align__(16) __half g_h1h[NMAX * 64];   // fp16 copy of h1 (gather src L2)
__device__ int    g_slot[NMAX * CAP];               // padded neighbor lists
__device__ int    g_cnt[NMAX];                      // in-degree
__device__ int    g_is64;

// --- edge-index dtype detection (int64 vs int32) ----------------------------
__global__ void detect_kernel(const void* ei) {
    const long long* q = (const long long*)ei;
    int is64 = 1;
    for (int i = 0; i < 128; i++) {
        long long v = q[i];
        if (v < 0 || v >= NMAX) { is64 = 0; break; }
    }
    g_is64 = is64;
}

// --- fused: zero degree counters + fp16 copy of x ---------------------------
__global__ void prep_kernel(const float* __restrict__ x, int N) {
    int i = blockIdx.x * blockDim.x + threadIdx.x;   // grid covers N*16
    if (i < N) g_cnt[i] = 0;
    if (i >= N * 16) return;
    float4 v = __ldg((const float4*)x + i);
    __half2 lo = __floats2half2_rn(v.x, v.y);
    __half2 hi = __floats2half2_rn(v.z, v.w);
    uint2 o;
    o.x = *(unsigned int*)&lo;
    o.y = *(unsigned int*)&hi;
    ((uint2*)g_xh)[i] = o;
}

// --- single-pass convert + bin ----------------------------------------------
__global__ void bin_kernel(const void* ei, int E) {
    int i = blockIdx.x * blockDim.x + threadIdx.x;
    if (i >= E) return;
    int s, d;
    if (g_is64) {
        const long long* q = (const long long*)ei;
        s = (int)q[i];
        d = (int)q[(size_t)E + i];
    } else {
        const int* q = (const int*)ei;
        s = q[i];
        d = q[E + i];
    }
    int pos = atomicAdd(&g_cnt[d], 1);
    if (pos < CAP) g_slot[d * CAP + pos] = s;
}

// --- gather aggregation over fp16 rows: 16 lanes/node, 8 B per lane ---------
// One neighbor row = 64 halves = 128 B = exactly one L2 line per half-warp.
// fp32 accumulation; writes the deg-normalized MEAN in fp32.
__global__ void aggregate_kernel(const float* __restrict__ tau,
                                 int useH1, int layer1, int N) {
    int t = blockIdx.x * blockDim.x + threadIdx.x;
    int n = t >> 4;
    int c = t & 15;        // lane handles cols [4c, 4c+4)
    if (n >= N) return;
    const __half* feat16 = useH1 ? g_h1h : g_xh;

    const int* lst = g_slot + n * CAP;
    int deg = g_cnt[n];
    int end = (deg < CAP) ? deg : CAP;
    float a0 = 0.f, a1 = 0.f, a2 = 0.f, a3 = 0.f;
    float ts = 0.f;

    int i = 0;
    for (; i + 4 <= end; i += 4) {
        int s0 = __ldg(lst + i);
        int s1 = __ldg(lst + i + 1);
        int s2 = __ldg(lst + i + 2);
        int s3 = __ldg(lst + i + 3);
        uint2 v0 = __ldg((const uint2*)(feat16 + (size_t)s0 * 64) + c);
        uint2 v1 = __ldg((const uint2*)(feat16 + (size_t)s1 * 64) + c);
        uint2 v2 = __ldg((const uint2*)(feat16 + (size_t)s2 * 64) + c);
        uint2 v3 = __ldg((const uint2*)(feat16 + (size_t)s3 * 64) + c);
        float2 f;
        f = __half22float2(*(__half2*)&v0.x); a0 += f.x; a1 += f.y;
        f = __half22float2(*(__half2*)&v0.y); a2 += f.x; a3 += f.y;
        f = __half22float2(*(__half2*)&v1.x); a0 += f.x; a1 += f.y;
        f = __half22float2(*(__half2*)&v1.y); a2 += f.x; a3 += f.y;
        f = __half22float2(*(__half2*)&v2.x); a0 += f.x; a1 += f.y;
        f = __half22float2(*(__half2*)&v2.y); a2 += f.x; a3 += f.y;
        f = __half22float2(*(__half2*)&v3.x); a0 += f.x; a1 += f.y;
        f = __half22float2(*(__half2*)&v3.y); a2 += f.x; a3 += f.y;
        if (layer1 && c == 0)
            ts += __ldg(tau + s0) + __ldg(tau + s1) + __ldg(tau + s2) + __ldg(tau + s3);
    }
    for (; i < end; i++) {
        int s0 = __ldg(lst + i);
        uint2 v0 = __ldg((const uint2*)(feat16 + (size_t)s0 * 64) + c);
        float2 f;
        f = __half22float2(*(__half2*)&v0.x); a0 += f.x; a1 += f.y;
        f = __half22float2(*(__half2*)&v0.y); a2 += f.x; a3 += f.y;
        if (layer1 && c == 0) ts += __ldg(tau + s0);
    }

    float inv = 1.0f / fmaxf((float)deg, 1.0f);
    float4 o;
    o.x = a0 * inv; o.y = a1 * inv; o.z = a2 * inv; o.w = a3 * inv;
    ((float4*)g_agg)[(size_t)n * 16 + c] = o;
    if (layer1 && c == 0) g_aggT[n] = ts * inv;
}

// --- packed f32x2 FMA helpers ----------------------------------------------
__device__ __forceinline__ unsigned long long pack2(float v) {
    unsigned long long r;
    asm("mov.b64 %0, {%1, %1};" : "=l"(r) : "r"(__float_as_uint(v)));
    return r;
}
__device__ __forceinline__ void ffma2(unsigned long long& d,
                                      unsigned long long a, unsigned long long b) {
    asm("fma.rn.f32x2 %0, %1, %2, %0;" : "+l"(d) : "l"(a), "l"(b));
}
__device__ __forceinline__ void unpack2(unsigned long long v, float& lo, float& hi) {
    unsigned int a, b;
    asm("mov.b64 {%0, %1}, %2;" : "=r"(a), "=r"(b) : "l"(v));
    lo = __uint_as_float(a); hi = __uint_as_float(b);
}
__device__ __forceinline__ unsigned long long packab(float a, float b) {
    unsigned long long r;
    asm("mov.b64 %0, {%1, %2};" : "=l"(r) : "r"(__float_as_uint(a)), "r"(__float_as_uint(b)));
    return r;
}

// --- layer 1 node update: h1 = relu(mean@W1l + b1l + [x|tau]@W1r) ----------
// Also emits the fp16 copy of h1 used by the layer-2 gather.
__global__ void node1_kernel(const float* __restrict__ x, const float* __restrict__ tau,
                             const float* __restrict__ W1l, const float* __restrict__ b1l,
                             const float* __restrict__ W1r, int N) {
    __shared__ __align__(16) float sWl[65 * 64];
    __shared__ __align__(16) float sWr[65 * 64];
    __shared__ float sb[64];
    for (int i = threadIdx.x; i < 65 * 64; i += blockDim.x) { sWl[i] = W1l[i]; sWr[i] = W1r[i]; }
    for (int i = threadIdx.x; i < 64; i += blockDim.x) sb[i] = b1l[i];
    __syncthreads();

    int n = blockIdx.x * blockDim.x + threadIdx.x;
    if (n >= N) return;

    unsigned long long acc[32];
#pragma unroll
    for (int o = 0; o < 32; o++) acc[o] = packab(sb[2 * o], sb[2 * o + 1]);

    const float* aggRow = g_agg + (size_t)n * 64;  // already mean
    const float* xRow   = x + (size_t)n * 64;

#pragma unroll 4
    for (int k = 0; k < 65; k++) {
        float am = (k < 64) ? aggRow[k] : g_aggT[n];
        float ax = (k < 64) ? xRow[k]   : tau[n];
        unsigned long long am2 = pack2(am);
        unsigned long long ax2 = pack2(ax);
        const ulonglong2* wl = (const ulonglong2*)(sWl + k * 64);
        const ulonglong2* wr = (const ulonglong2*)(sWr + k * 64);
#pragma unroll
        for (int o = 0; o < 16; o++) {
            ulonglong2 l = wl[o];
            ulonglong2 r = wr[o];
            ffma2(acc[2 * o + 0], am2, l.x);
            ffma2(acc[2 * o + 0], ax2, r.x);
            ffma2(acc[2 * o + 1], am2, l.y);
            ffma2(acc[2 * o + 1], ax2, r.y);
        }
    }

    float4* outRow  = (float4*)(g_h1 + (size_t)n * 64);
    uint2*  outRowH = (uint2*)(g_h1h + (size_t)n * 64);
#pragma unroll
    for (int o = 0; o < 16; o++) {
        float a0, a1, a2, a3;
        unpack2(acc[2 * o + 0], a0, a1);
        unpack2(acc[2 * o + 1], a2, a3);
        float4 v;
        v.x = fmaxf(a0, 0.f); v.y = fmaxf(a1, 0.f);
        v.z = fmaxf(a2, 0.f); v.w = fmaxf(a3, 0.f);
        outRow[o] = v;
        __half2 lo = __floats2half2_rn(v.x, v.y);
        __half2 hi = __floats2half2_rn(v.z, v.w);
        uint2 hv;
        hv.x = *(unsigned int*)&lo;
        hv.y = *(unsigned int*)&hi;
        outRowH[o] = hv;
    }
}

// --- layer 2 node update + fused fc head -----------------------------------
__global__ void node2_kernel(const float* __restrict__ W2l, const float* __restrict__ b2l,
                             const float* __restrict__ W2r, const float* __restrict__ Wfc,
                             const float* __restrict__ bfc, float* __restrict__ out, int N) {
    __shared__ __align__(16) float sWl[64 * 64];
    __shared__ __align__(16) float sWr[64 * 64];
    __shared__ float sb[64];
    __shared__ float sfc[64];
    for (int i = threadIdx.x; i < 64 * 64; i += blockDim.x) { sWl[i] = W2l[i]; sWr[i] = W2r[i]; }
    for (int i = threadIdx.x; i < 64; i += blockDim.x) { sb[i] = b2l[i]; sfc[i] = Wfc[i]; }
    __syncthreads();

    int n = blockIdx.x * blockDim.x + threadIdx.x;
    if (n >= N) return;

    unsigned long long acc[32];
#pragma unroll
    for (int o = 0; o < 32; o++) acc[o] = packab(sb[2 * o], sb[2 * o + 1]);

    const float* aggRow = g_agg + (size_t)n * 64;  // already mean
    const float* hRow   = g_h1 + (size_t)n * 64;

#pragma unroll 4
    for (int k = 0; k < 64; k++) {
        unsigned long long am2 = pack2(aggRow[k]);
        unsigned long long ax2 = pack2(hRow[k]);
        const ulonglong2* wl = (const ulonglong2*)(sWl + k * 64);
        const ulonglong2* wr = (const ulonglong2*)(sWr + k * 64);
#pragma unroll
        for (int o = 0; o < 16; o++) {
            ulonglong2 l = wl[o];
            ulonglong2 r = wr[o];
            ffma2(acc[2 * o + 0], am2, l.x);
            ffma2(acc[2 * o + 0], ax2, r.x);
            ffma2(acc[2 * o + 1], am2, l.y);
            ffma2(acc[2 * o + 1], ax2, r.y);
        }
    }

    float r = __ldg(bfc);
#pragma unroll
    for (int o = 0; o < 32; o++) {
        float a0, a1;
        unpack2(acc[o], a0, a1);
        r += fmaxf(a0, 0.f) * sfc[2 * o] + fmaxf(a1, 0.f) * sfc[2 * o + 1];
    }
    out[n] = r;
}

// ---------------------------------------------------------------------------
extern "C" void kernel_launch(void* const* d_in, const int* in_sizes, int n_in,
                              void* d_out, int out_size) {
    const float* x   = (const float*)d_in[0];
    const void*  ei  = d_in[1];
    const float* tau = (const float*)d_in[2];
    const float* W1l = (const float*)d_in[3];
    const float* b1l = (const float*)d_in[4];
    const float* W1r = (const float*)d_in[5];
    const float* W2l = (const float*)d_in[6];
    const float* b2l = (const float*)d_in[7];
    const float* W2r = (const float*)d_in[8];
    const float* Wfc = (const float*)d_in[9];
    const float* bfc = (const float*)d_in[10];

    int N = in_sizes[0] / 64;
    int E = in_sizes[1] / 2;
    int eb = (E + 255) / 256;
    int ab = (N * 16 + 255) / 256;

    // ---- binning (once per launch) + fp16 copy of x ----
    detect_kernel<<<1, 1>>>(ei);
    prep_kernel<<<ab, 256>>>(x, N);
    bin_kernel<<<eb, 256>>>(ei, E);

    // ---- layer 1 ----
    aggregate_kernel<<<ab, 256>>>(tau, 0, 1, N);
    node1_kernel<<<(N + 127) / 128, 128>>>(x, tau, W1l, b1l, W1r, N);

    // ---- layer 2 (+ fused fc) ----
    aggregate_kernel<<<ab, 256>>>(tau, 1, 0, N);
    node2_kernel<<<(N + 127) / 128, 128>>>(W2l, b2l, W2r, Wfc, bfc, (float*)d_out, N);
}

// round 17
// speedup vs baseline: 1.0618x; 1.0618x over previous
#include <cuda_runtime.h>
#include <cuda_fp16.h>

// ---------------------------------------------------------------------------
// GQNN: 2-layer SAGEConv (mean aggr) + fc head, CSR-gather formulation.
//   CSR build (hist/scan/bin, reading the raw edge list twice — it is
//   L2-resident) once per launch; per layer:
//     mean = CSR gather of fp16 neighbor rows, 8 lanes/node x uint4 (16B),
//            fp32 accumulate, no atomics
//     h    = relu(mean @ Wl + b + h_prev @ Wr)   [f32x2 packed FMA]
// N = 100000, E = 3200000, HID = 64.
// NOTE: __device__ buffers are selected INSIDE device code (flag arg).
// ---------------------------------------------------------------------------

#define NMAX 100000
#define EMAX 3200000
#define SCAN_B 1024
#define NBLK ((NMAX + SCAN_B - 1) / SCAN_B)   // 98

__device__ __align__(16) float  g_agg[NMAX * 64];   // neighbor MEAN (fp32)
__device__ float  g_aggT[NMAX];                     // tau mean (layer 1 only)
__device__ __align__(16) float  g_h1[NMAX * 64];    // layer-1 output (fp32, self term)
__device__ __align__(16) __half g_xh[NMAX * 64];    // fp16 copy of x (gather src L1)
__device__ __align__(16) __half g_h1h[NMAX * 64];   // fp16 copy of h1 (gather src L2)
__device__ int    g_csr[EMAX];        // src indices binned by dst
__device__ int    g_cnt[NMAX];
__device__ int    g_part[NMAX];
__device__ int    g_off[NMAX + 1];
__device__ int    g_cursor[NMAX];
__device__ int    g_bsum[NBLK];
__device__ int    g_bpre[NBLK];
__device__ int    g_is64;

// --- edge-index dtype detection (int64 vs int32) ----------------------------
__global__ void detect_kernel(const void* ei) {
    const long long* q = (const long long*)ei;
    int is64 = 1;
    for (int i = 0; i < 128; i++) {
        long long v = q[i];
        if (v < 0 || v >= NMAX) { is64 = 0; break; }
    }
    g_is64 = is64;
}

// --- fused: zero degree counters + fp16 copy of x ---------------------------
__global__ void prep_kernel(const float* __restrict__ x, int N) {
    int i = blockIdx.x * blockDim.x + threadIdx.x;   // grid covers N*16
    if (i < N) g_cnt[i] = 0;
    if (i >= N * 16) return;
    float4 v = __ldg((const float4*)x + i);
    __half2 lo = __floats2half2_rn(v.x, v.y);
    __half2 hi = __floats2half2_rn(v.z, v.w);
    uint2 o;
    o.x = *(unsigned int*)&lo;
    o.y = *(unsigned int*)&hi;
    ((uint2*)g_xh)[i] = o;
}

// --- histogram dst degrees (reads raw edge list) ----------------------------
__global__ void hist_kernel(const void* ei, int E) {
    int i = blockIdx.x * blockDim.x + threadIdx.x;
    if (i >= E) return;
    int d;
    if (g_is64) d = (int)((const long long*)ei)[(size_t)E + i];
    else        d = ((const int*)ei)[E + i];
    atomicAdd(&g_cnt[d], 1);
}

// --- 3-kernel exclusive scan of g_cnt --------------------------------------
__global__ void scan1_kernel(int N) {
    __shared__ int sm[SCAN_B];
    int i = blockIdx.x * SCAN_B + threadIdx.x;
    int v = (i < N) ? g_cnt[i] : 0;
    sm[threadIdx.x] = v;
    __syncthreads();
    for (int off = 1; off < SCAN_B; off <<= 1) {
        int t = (threadIdx.x >= off) ? sm[threadIdx.x - off] : 0;
        __syncthreads();
        sm[threadIdx.x] += t;
        __syncthreads();
    }
    if (i < N) g_part[i] = sm[threadIdx.x] - v;
    if (threadIdx.x == SCAN_B - 1) g_bsum[blockIdx.x] = sm[SCAN_B - 1];
}

__global__ void scan2_kernel(int nb, int N, int E) {
    __shared__ int sm[128];
    int v = (threadIdx.x < nb) ? g_bsum[threadIdx.x] : 0;
    sm[threadIdx.x] = v;
    __syncthreads();
    for (int off = 1; off < 128; off <<= 1) {
        int t = (threadIdx.x >= off) ? sm[threadIdx.x - off] : 0;
        __syncthreads();
        sm[threadIdx.x] += t;
        __syncthreads();
    }
    if (threadIdx.x < nb) g_bpre[threadIdx.x] = sm[threadIdx.x] - v;
    if (threadIdx.x == 0) g_off[N] = E;
}

__global__ void scan3_kernel(int N) {
    int i = blockIdx.x * SCAN_B + threadIdx.x;
    if (i < N) {
        int o = g_part[i] + g_bpre[blockIdx.x];
        g_off[i] = o;
        g_cursor[i] = o;
    }
}

// --- bin edges into CSR (re-reads raw edge list; it is L2-resident) ---------
__global__ void build_kernel(const void* ei, int E) {
    int i = blockIdx.x * blockDim.x + threadIdx.x;
    if (i >= E) return;
    int s, d;
    if (g_is64) {
        const long long* q = (const long long*)ei;
        s = (int)q[i];
        d = (int)q[(size_t)E + i];
    } else {
        const int* q = (const int*)ei;
        s = q[i];
        d = q[E + i];
    }
    int pos = atomicAdd(&g_cursor[d], 1);
    g_csr[pos] = s;
}

// --- CSR gather aggregation over fp16 rows: 8 lanes/node, 16 B per lane -----
// One neighbor row = 64 halves = 128 B = one L2 line per 8-lane group.
// uint4 loads: 2x bytes in flight per lane, half the index-load redundancy.
// fp32 accumulation; writes the deg-normalized MEAN in fp32.
__global__ void aggregate_kernel(const float* __restrict__ tau,
                                 int useH1, int layer1, int N) {
    int t = blockIdx.x * blockDim.x + threadIdx.x;
    int n = t >> 3;
    int c = t & 7;         // lane handles cols [8c, 8c+8)
    if (n >= N) return;
    const __half* feat16 = useH1 ? g_h1h : g_xh;

    int beg = g_off[n];
    int end = g_off[n + 1];
    float a0 = 0.f, a1 = 0.f, a2 = 0.f, a3 = 0.f;
    float a4 = 0.f, a5 = 0.f, a6 = 0.f, a7 = 0.f;
    float ts = 0.f;

    int i = beg;
    for (; i + 4 <= end; i += 4) {
        int s0 = __ldg(g_csr + i);
        int s1 = __ldg(g_csr + i + 1);
        int s2 = __ldg(g_csr + i + 2);
        int s3 = __ldg(g_csr + i + 3);
        uint4 v0 = __ldg((const uint4*)(feat16 + (size_t)s0 * 64) + c);
        uint4 v1 = __ldg((const uint4*)(feat16 + (size_t)s1 * 64) + c);
        uint4 v2 = __ldg((const uint4*)(feat16 + (size_t)s2 * 64) + c);
        uint4 v3 = __ldg((const uint4*)(feat16 + (size_t)s3 * 64) + c);
        float2 f;
        f = __half22float2(*(__half2*)&v0.x); a0 += f.x; a1 += f.y;
        f = __half22float2(*(__half2*)&v0.y); a2 += f.x; a3 += f.y;
        f = __half22float2(*(__half2*)&v0.z); a4 += f.x; a5 += f.y;
        f = __half22float2(*(__half2*)&v0.w); a6 += f.x; a7 += f.y;
        f = __half22float2(*(__half2*)&v1.x); a0 += f.x; a1 += f.y;
        f = __half22float2(*(__half2*)&v1.y); a2 += f.x; a3 += f.y;
        f = __half22float2(*(__half2*)&v1.z); a4 += f.x; a5 += f.y;
        f = __half22float2(*(__half2*)&v1.w); a6 += f.x; a7 += f.y;
        f = __half22float2(*(__half2*)&v2.x); a0 += f.x; a1 += f.y;
        f = __half22float2(*(__half2*)&v2.y); a2 += f.x; a3 += f.y;
        f = __half22float2(*(__half2*)&v2.z); a4 += f.x; a5 += f.y;
        f = __half22float2(*(__half2*)&v2.w); a6 += f.x; a7 += f.y;
        f = __half22float2(*(__half2*)&v3.x); a0 += f.x; a1 += f.y;
        f = __half22float2(*(__half2*)&v3.y); a2 += f.x; a3 += f.y;
        f = __half22float2(*(__half2*)&v3.z); a4 += f.x; a5 += f.y;
        f = __half22float2(*(__half2*)&v3.w); a6 += f.x; a7 += f.y;
        if (layer1 && c == 0)
            ts += __ldg(tau + s0) + __ldg(tau + s1) + __ldg(tau + s2) + __ldg(tau + s3);
    }
    for (; i < end; i++) {
        int s0 = __ldg(g_csr + i);
        uint4 v0 = __ldg((const uint4*)(feat16 + (size_t)s0 * 64) + c);
        float2 f;
        f = __half22float2(*(__half2*)&v0.x); a0 += f.x; a1 += f.y;
        f = __half22float2(*(__half2*)&v0.y); a2 += f.x; a3 += f.y;
        f = __half22float2(*(__half2*)&v0.z); a4 += f.x; a5 += f.y;
        f = __half22float2(*(__half2*)&v0.w); a6 += f.x; a7 += f.y;
        if (layer1 && c == 0) ts += __ldg(tau + s0);
    }

    float inv = 1.0f / fmaxf((float)(end - beg), 1.0f);
    float4 o0, o1;
    o0.x = a0 * inv; o0.y = a1 * inv; o0.z = a2 * inv; o0.w = a3 * inv;
    o1.x = a4 * inv; o1.y = a5 * inv; o1.z = a6 * inv; o1.w = a7 * inv;
    ((float4*)g_agg)[(size_t)n * 16 + 2 * c + 0] = o0;
    ((float4*)g_agg)[(size_t)n * 16 + 2 * c + 1] = o1;
    if (layer1 && c == 0) g_aggT[n] = ts * inv;
}

// --- packed f32x2 FMA helpers ----------------------------------------------
__device__ __forceinline__ unsigned long long pack2(float v) {
    unsigned long long r;
    asm("mov.b64 %0, {%1, %1};" : "=l"(r) : "r"(__float_as_uint(v)));
    return r;
}
__device__ __forceinline__ void ffma2(unsigned long long& d,
                                      unsigned long long a, unsigned long long b) {
    asm("fma.rn.f32x2 %0, %1, %2, %0;" : "+l"(d) : "l"(a), "l"(b));
}
__device__ __forceinline__ void unpack2(unsigned long long v, float& lo, float& hi) {
    unsigned int a, b;
    asm("mov.b64 {%0, %1}, %2;" : "=r"(a), "=r"(b) : "l"(v));
    lo = __uint_as_float(a); hi = __uint_as_float(b);
}
__device__ __forceinline__ unsigned long long packab(float a, float b) {
    unsigned long long r;
    asm("mov.b64 %0, {%1, %2};" : "=l"(r) : "r"(__float_as_uint(a)), "r"(__float_as_uint(b)));
    return r;
}

// --- layer 1 node update: h1 = relu(mean@W1l + b1l + [x|tau]@W1r) ----------
// Also emits the fp16 copy of h1 used by the layer-2 gather.
__global__ void node1_kernel(const float* __restrict__ x, const float* __restrict__ tau,
                             const float* __restrict__ W1l, const float* __restrict__ b1l,
                             const float* __restrict__ W1r, int N) {
    __shared__ __align__(16) float sWl[65 * 64];
    __shared__ __align__(16) float sWr[65 * 64];
    __shared__ float sb[64];
    for (int i = threadIdx.x; i < 65 * 64; i += blockDim.x) { sWl[i] = W1l[i]; sWr[i] = W1r[i]; }
    for (int i = threadIdx.x; i < 64; i += blockDim.x) sb[i] = b1l[i];
    __syncthreads();

    int n = blockIdx.x * blockDim.x + threadIdx.x;
    if (n >= N) return;

    unsigned long long acc[32];
#pragma unroll
    for (int o = 0; o < 32; o++) acc[o] = packab(sb[2 * o], sb[2 * o + 1]);

    const float* aggRow = g_agg + (size_t)n * 64;  // already mean
    const float* xRow   = x + (size_t)n * 64;

#pragma unroll 4
    for (int k = 0; k < 65; k++) {
        float am = (k < 64) ? aggRow[k] : g_aggT[n];
        float ax = (k < 64) ? xRow[k]   : tau[n];
        unsigned long long am2 = pack2(am);
        unsigned long long ax2 = pack2(ax);
        const ulonglong2* wl = (const ulonglong2*)(sWl + k * 64);
        const ulonglong2* wr = (const ulonglong2*)(sWr + k * 64);
#pragma unroll
        for (int o = 0; o < 16; o++) {
            ulonglong2 l = wl[o];
            ulonglong2 r = wr[o];
            ffma2(acc[2 * o + 0], am2, l.x);
            ffma2(acc[2 * o + 0], ax2, r.x);
            ffma2(acc[2 * o + 1], am2, l.y);
            ffma2(acc[2 * o + 1], ax2, r.y);
        }
    }

    float4* outRow  = (float4*)(g_h1 + (size_t)n * 64);
    uint2*  outRowH = (uint2*)(g_h1h + (size_t)n * 64);
#pragma unroll
    for (int o = 0; o < 16; o++) {
        float a0, a1, a2, a3;
        unpack2(acc[2 * o + 0], a0, a1);
        unpack2(acc[2 * o + 1], a2, a3);
        float4 v;
        v.x = fmaxf(a0, 0.f); v.y = fmaxf(a1, 0.f);
        v.z = fmaxf(a2, 0.f); v.w = fmaxf(a3, 0.f);
        outRow[o] = v;
        __half2 lo = __floats2half2_rn(v.x, v.y);
        __half2 hi = __floats2half2_rn(v.z, v.w);
        uint2 hv;
        hv.x = *(unsigned int*)&lo;
        hv.y = *(unsigned int*)&hi;
        outRowH[o] = hv;
    }
}

// --- layer 2 node update + fused fc head -----------------------------------
__global__ void node2_kernel(const float* __restrict__ W2l, const float* __restrict__ b2l,
                             const float* __restrict__ W2r, const float* __restrict__ Wfc,
                             const float* __restrict__ bfc, float* __restrict__ out, int N) {
    __shared__ __align__(16) float sWl[64 * 64];
    __shared__ __align__(16) float sWr[64 * 64];
    __shared__ float sb[64];
    __shared__ float sfc[64];
    for (int i = threadIdx.x; i < 64 * 64; i += blockDim.x) { sWl[i] = W2l[i]; sWr[i] = W2r[i]; }
    for (int i = threadIdx.x; i < 64; i += blockDim.x) { sb[i] = b2l[i]; sfc[i] = Wfc[i]; }
    __syncthreads();

    int n = blockIdx.x * blockDim.x + threadIdx.x;
    if (n >= N) return;

    unsigned long long acc[32];
#pragma unroll
    for (int o = 0; o < 32; o++) acc[o] = packab(sb[2 * o], sb[2 * o + 1]);

    const float* aggRow = g_agg + (size_t)n * 64;  // already mean
    const float* hRow   = g_h1 + (size_t)n * 64;

#pragma unroll 4
    for (int k = 0; k < 64; k++) {
        unsigned long long am2 = pack2(aggRow[k]);
        unsigned long long ax2 = pack2(hRow[k]);
        const ulonglong2* wl = (const ulonglong2*)(sWl + k * 64);
        const ulonglong2* wr = (const ulonglong2*)(sWr + k * 64);
#pragma unroll
        for (int o = 0; o < 16; o++) {
            ulonglong2 l = wl[o];
            ulonglong2 r = wr[o];
            ffma2(acc[2 * o + 0], am2, l.x);
            ffma2(acc[2 * o + 0], ax2, r.x);
            ffma2(acc[2 * o + 1], am2, l.y);
            ffma2(acc[2 * o + 1], ax2, r.y);
        }
    }

    float r = __ldg(bfc);
#pragma unroll
    for (int o = 0; o < 32; o++) {
        float a0, a1;
        unpack2(acc[o], a0, a1);
        r += fmaxf(a0, 0.f) * sfc[2 * o] + fmaxf(a1, 0.f) * sfc[2 * o + 1];
    }
    out[n] = r;
}

// ---------------------------------------------------------------------------
extern "C" void kernel_launch(void* const* d_in, const int* in_sizes, int n_in,
                              void* d_out, int out_size) {
    const float* x   = (const float*)d_in[0];
    const void*  ei  = d_in[1];
    const float* tau = (const float*)d_in[2];
    const float* W1l = (const float*)d_in[3];
    const float* b1l = (const float*)d_in[4];
    const float* W1r = (const float*)d_in[5];
    const float* W2l = (const float*)d_in[6];
    const float* b2l = (const float*)d_in[7];
    const float* W2r = (const float*)d_in[8];
    const float* Wfc = (const float*)d_in[9];
    const float* bfc = (const float*)d_in[10];

    int N = in_sizes[0] / 64;
    int E = in_sizes[1] / 2;
    int nb = (N + SCAN_B - 1) / SCAN_B;
    int eb = (E + 255) / 256;
    int pb = (N * 16 + 255) / 256;
    int ab = (N * 8 + 255) / 256;

    // ---- CSR build (once per launch) + fp16 copy of x ----
    detect_kernel<<<1, 1>>>(ei);
    prep_kernel<<<pb, 256>>>(x, N);
    hist_kernel<<<eb, 256>>>(ei, E);
    scan1_kernel<<<nb, SCAN_B>>>(N);
    scan2_kernel<<<1, 128>>>(nb, N, E);
    scan3_kernel<<<nb, SCAN_B>>>(N);
    build_kernel<<<eb, 256>>>(ei, E);

    // ---- layer 1 ----
    aggregate_kernel<<<ab, 256>>>(tau, 0, 1, N);
    node1_kernel<<<(N + 127) / 128, 128>>>(x, tau, W1l, b1l, W1r, N);

    // ---- layer 2 (+ fused fc) ----
    aggregate_kernel<<<ab, 256>>>(tau, 1, 0, N);
    node2_kernel<<<(N + 127) / 128, 128>>>(W2l, b2l, W2r, Wfc, bfc, (float*)d_out, N);
}